// round 1
// baseline (speedup 1.0000x reference)
#include <cuda_runtime.h>
#include <math.h>

#define LT 2048      // tokens (B*L)
#define DMODEL 1024
#define EDIM 2048
#define KCONV 4
#define NSTATE 16
#define DTR 64
#define NEXP 8
#define FFD 2048
#define XPJ 96       // DTR + 2*NSTATE

// ------------------------- static device scratch -------------------------
static __device__ float g_h1[(size_t)LT * DMODEL];
static __device__ float g_xz[(size_t)LT * 2 * EDIM];
static __device__ float g_xc[(size_t)LT * EDIM];
static __device__ float g_dbc[(size_t)LT * XPJ];
static __device__ float g_delta[(size_t)LT * EDIM];
static __device__ float g_y[(size_t)LT * EDIM];
static __device__ float g_x2[(size_t)LT * DMODEL];
static __device__ float g_h2[(size_t)LT * DMODEL];
static __device__ float g_hg[(size_t)2 * LT * FFD];
static __device__ float g_hu[(size_t)2 * LT * FFD];
static __device__ int   g_sel[LT * 2];
static __device__ float g_selw[LT * 2];
static __device__ int   g_counts[NEXP];
static __device__ int   g_offs[NEXP];
static __device__ int   g_cursor[NEXP];
static __device__ int   g_perm[2 * LT];
static __device__ float g_pw[2 * LT];

__device__ __forceinline__ float siluf(float v) { return v / (1.f + expf(-v)); }
__device__ __forceinline__ float softplusf(float v) {
    return v > 0.f ? v + log1pf(expf(-v)) : log1pf(expf(v));
}

// ------------------------- small kernels -------------------------
__global__ void reset_kernel() {
    int i = threadIdx.x;
    if (i < NEXP) { g_counts[i] = 0; g_cursor[i] = 0; }
}

// one block per row; optionally copies the (pre-norm) input row to copy_out
__global__ void rmsnorm_kernel(const float* __restrict__ x, const float* __restrict__ w,
                               float* __restrict__ out, float* __restrict__ copy_out) {
    int row = blockIdx.x;
    int tid = threadIdx.x;
    const float* xr = x + (size_t)row * DMODEL;
    float s = 0.f;
    for (int i = tid; i < DMODEL; i += 256) { float v = xr[i]; s += v * v; }
    __shared__ float sh[9];
    for (int o = 16; o > 0; o >>= 1) s += __shfl_xor_sync(0xffffffffu, s, o);
    if ((tid & 31) == 0) sh[tid >> 5] = s;
    __syncthreads();
    if (tid == 0) {
        float t = 0.f;
        for (int i = 0; i < 8; i++) t += sh[i];
        sh[8] = t;
    }
    __syncthreads();
    float scale = rsqrtf(sh[8] * (1.f / DMODEL) + 1e-6f);
    for (int i = tid; i < DMODEL; i += 256) {
        float v = xr[i];
        out[(size_t)row * DMODEL + i] = v * scale * w[i];
        if (copy_out) copy_out[(size_t)row * DMODEL + i] = v;
    }
}

// xc[t,e] = silu(b[e] + sum_k w[e,k] * xm[t-3+k, e]); xm = g_xz[:, :EDIM]
__global__ void conv_silu_kernel(const float* __restrict__ cw, const float* __restrict__ cb) {
    int idx = blockIdx.x * blockDim.x + threadIdx.x;
    if (idx >= LT * EDIM) return;
    int t = idx / EDIM, e = idx - t * EDIM;
    float acc = cb[e];
#pragma unroll
    for (int k = 0; k < KCONV; k++) {
        int tt = t - (KCONV - 1) + k;
        if (tt >= 0) acc = fmaf(cw[e * KCONV + k], g_xz[(size_t)tt * 2 * EDIM + e], acc);
    }
    g_xc[idx] = siluf(acc);
}

// selective scan: thread = (channel e, state n); 16-lane shuffle reduce over n
__global__ void scan_kernel(const float* __restrict__ A_log, const float* __restrict__ D_skip) {
    int gid = blockIdx.x * blockDim.x + threadIdx.x;
    int e = gid >> 4, n = gid & 15;
    if (e >= EDIM) return;
    float Ae = -expf(A_log[e * NSTATE + n]);
    float Dsk = D_skip[e];
    float h = 0.f;
    for (int t = 0; t < LT; t++) {
        float dlt = g_delta[(size_t)t * EDIM + e];
        float xct = g_xc[(size_t)t * EDIM + e];
        float Bn = g_dbc[(size_t)t * XPJ + DTR + n];
        float Cn = g_dbc[(size_t)t * XPJ + DTR + NSTATE + n];
        float dA = expf(dlt * Ae);
        h = fmaf(dA, h, dlt * Bn * xct);
        float p = h * Cn;
        p += __shfl_xor_sync(0xffffffffu, p, 8);
        p += __shfl_xor_sync(0xffffffffu, p, 4);
        p += __shfl_xor_sync(0xffffffffu, p, 2);
        p += __shfl_xor_sync(0xffffffffu, p, 1);
        if (n == 0) {
            float zt = g_xz[(size_t)t * 2 * EDIM + EDIM + e];
            g_y[(size_t)t * EDIM + e] = (p + Dsk * xct) * siluf(zt);
        }
    }
}

// router: block per token; 8 groups of 16 lanes, each a dot over DMODEL
__global__ void router_kernel(const float* __restrict__ Wr, float* __restrict__ out_logits) {
    int t = blockIdx.x;
    int tid = threadIdx.x;
    int g = tid >> 4, l = tid & 15;
    const float* xr = g_h2 + (size_t)t * DMODEL;
    const float* wr = Wr + (size_t)g * DMODEL;
    float acc = 0.f;
    for (int d = l; d < DMODEL; d += 16) acc = fmaf(xr[d], wr[d], acc);
    acc += __shfl_xor_sync(0xffffffffu, acc, 8);
    acc += __shfl_xor_sync(0xffffffffu, acc, 4);
    acc += __shfl_xor_sync(0xffffffffu, acc, 2);
    acc += __shfl_xor_sync(0xffffffffu, acc, 1);
    __shared__ float slog[NEXP];
    if (l == 0) slog[g] = acc;
    __syncthreads();
    if (tid == 0) {
        float lg[NEXP];
        float m = -1e30f;
        for (int e = 0; e < NEXP; e++) {
            lg[e] = slog[e];
            out_logits[(size_t)t * NEXP + e] = lg[e];
            m = fmaxf(m, lg[e]);
        }
        float den = 0.f;
        for (int e = 0; e < NEXP; e++) den += expf(lg[e] - m);
        int i0 = 0; float b0 = -1e30f;
        for (int e = 0; e < NEXP; e++) if (lg[e] > b0) { b0 = lg[e]; i0 = e; }
        int i1 = 0; float b1 = -1e30f;
        for (int e = 0; e < NEXP; e++) if (e != i0 && lg[e] > b1) { b1 = lg[e]; i1 = e; }
        g_sel[t * 2 + 0] = i0;  g_selw[t * 2 + 0] = expf(b0 - m) / den;
        g_sel[t * 2 + 1] = i1;  g_selw[t * 2 + 1] = expf(b1 - m) / den;
        atomicAdd(&g_counts[i0], 1);
        atomicAdd(&g_counts[i1], 1);
    }
}

__global__ void offsets_kernel() {
    if (threadIdx.x == 0) {
        int s = 0;
        for (int e = 0; e < NEXP; e++) { g_offs[e] = s; s += g_counts[e]; }
    }
}

__global__ void scatter_kernel() {
    int t = blockIdx.x * blockDim.x + threadIdx.x;
    if (t >= LT) return;
#pragma unroll
    for (int i = 0; i < 2; i++) {
        int e = g_sel[t * 2 + i];
        int pos = g_offs[e] + atomicAdd(&g_cursor[e], 1);
        g_perm[pos] = t;
        g_pw[pos] = g_selw[t * 2 + i];
    }
}

__global__ void silu_mul_kernel() {
    size_t idx = (size_t)blockIdx.x * blockDim.x + threadIdx.x;
    if (idx >= (size_t)2 * LT * FFD) return;
    float gv = g_hg[idx];
    g_hg[idx] = siluf(gv) * g_hu[idx];
}

// ------------------------- generic NT SGEMM -------------------------
// C[M,N] = A[M,K] @ B[N,K]^T   (both K-major), 128x128x8 tiles, 8x8/thread.
// MODE 0: plain store (N may be < tile; K-aligned to 8, M to 128)
// MODE 1: C = softplus(acc + aux[col])
// MODE 2: C = acc + aux[row*ldc+col]
// MODE 3: per-expert gather GEMM: A rows gathered via g_perm, store grouped rows
// MODE 4: per-expert GEMM, epilogue atomicAdd(out[token], w*acc)
template <int MODE>
__global__ void __launch_bounds__(256)
sgemm_nt(const float* __restrict__ A, int lda,
         const float* __restrict__ B, int ldb, long bstride,
         float* __restrict__ C, int ldc,
         int N, int K,
         const float* __restrict__ aux) {
    const int BM = 128, BN = 128, BK = 8;
    __shared__ float As[BK][BM];
    __shared__ float Bs[BK][BN];
    __shared__ int stok[BM];
    __shared__ float swt[BM];

    int tid = threadIdx.x;
    int bx = blockIdx.x, by = blockIdx.y, ez = blockIdx.z;

    int cnt = 1 << 30, off = 0;
    const float* Bp = B;
    if (MODE == 3 || MODE == 4) {
        cnt = g_counts[ez];
        off = g_offs[ez];
        if (by * BM >= cnt) return;
        Bp = B + (long)ez * bstride;
        if (tid < BM) {
            int r = by * BM + tid;
            stok[tid] = (r < cnt) ? g_perm[off + r] : -1;
            if (MODE == 4) swt[tid] = (r < cnt) ? g_pw[off + r] : 0.f;
        }
        __syncthreads();
    }

    int ar = tid >> 1;
    int ak = (tid & 1) * 4;
    long arow;
    bool avalid = true;
    if (MODE == 3) { int tok = stok[ar]; avalid = (tok >= 0); arow = (tok >= 0) ? tok : 0; }
    else if (MODE == 4) { int r = by * BM + ar; avalid = (r < cnt); arow = (long)off + r; }
    else arow = (long)by * BM + ar;
    int brow = bx * BN + ar;
    bool bvalid = brow < N;
    const float* Aptr = A + arow * (long)lda + ak;
    const float* Bptr = Bp + (long)brow * ldb + ak;

    float acc[8][8];
#pragma unroll
    for (int i = 0; i < 8; i++)
#pragma unroll
        for (int j = 0; j < 8; j++) acc[i][j] = 0.f;

    int tx = tid & 15, ty = tid >> 4;

    for (int k0 = 0; k0 < K; k0 += BK) {
        float4 av = avalid ? *(const float4*)(Aptr + k0) : make_float4(0, 0, 0, 0);
        float4 bv = bvalid ? *(const float4*)(Bptr + k0) : make_float4(0, 0, 0, 0);
        As[ak + 0][ar] = av.x; As[ak + 1][ar] = av.y; As[ak + 2][ar] = av.z; As[ak + 3][ar] = av.w;
        Bs[ak + 0][ar] = bv.x; Bs[ak + 1][ar] = bv.y; Bs[ak + 2][ar] = bv.z; Bs[ak + 3][ar] = bv.w;
        __syncthreads();
        float a[8], b[8];
#pragma unroll
        for (int kk = 0; kk < BK; kk++) {
            *(float4*)&a[0] = *(const float4*)&As[kk][ty * 4];
            *(float4*)&a[4] = *(const float4*)&As[kk][64 + ty * 4];
            *(float4*)&b[0] = *(const float4*)&Bs[kk][tx * 4];
            *(float4*)&b[4] = *(const float4*)&Bs[kk][64 + tx * 4];
#pragma unroll
            for (int i = 0; i < 8; i++)
#pragma unroll
                for (int j = 0; j < 8; j++) acc[i][j] = fmaf(a[i], b[j], acc[i][j]);
        }
        __syncthreads();
    }

#pragma unroll
    for (int i = 0; i < 8; i++) {
        int ml = (i < 4) ? (ty * 4 + i) : (64 + ty * 4 + (i - 4));
#pragma unroll
        for (int jh = 0; jh < 2; jh++) {
            int nl = jh * 64 + tx * 4;
            int col = bx * BN + nl;
            float v0 = acc[i][jh * 4 + 0], v1 = acc[i][jh * 4 + 1];
            float v2 = acc[i][jh * 4 + 2], v3 = acc[i][jh * 4 + 3];
            if (MODE == 0) {
                if (col < N) {
                    long row = (long)by * BM + ml;
                    *(float4*)(C + row * ldc + col) = make_float4(v0, v1, v2, v3);
                }
            } else if (MODE == 1) {
                long row = (long)by * BM + ml;
                *(float4*)(C + row * ldc + col) =
                    make_float4(softplusf(v0 + aux[col + 0]), softplusf(v1 + aux[col + 1]),
                                softplusf(v2 + aux[col + 2]), softplusf(v3 + aux[col + 3]));
            } else if (MODE == 2) {
                long row = (long)by * BM + ml;
                float4 r4 = *(const float4*)(aux + row * ldc + col);
                *(float4*)(C + row * ldc + col) =
                    make_float4(v0 + r4.x, v1 + r4.y, v2 + r4.z, v3 + r4.w);
            } else if (MODE == 3) {
                if (by * BM + ml < cnt) {
                    long row = (long)off + by * BM + ml;
                    *(float4*)(C + row * ldc + col) = make_float4(v0, v1, v2, v3);
                }
            } else {  // MODE 4
                if (by * BM + ml < cnt) {
                    int tok = stok[ml];
                    float w = swt[ml];
                    float* o = C + (long)tok * ldc + col;
                    atomicAdd(o + 0, w * v0);
                    atomicAdd(o + 1, w * v1);
                    atomicAdd(o + 2, w * v2);
                    atomicAdd(o + 3, w * v3);
                }
            }
        }
    }
}

// ------------------------- host launcher -------------------------
extern "C" void kernel_launch(void* const* d_in, const int* in_sizes, int n_in,
                              void* d_out, int out_size) {
    const float* x       = (const float*)d_in[0];
    const float* rms1_w  = (const float*)d_in[1];
    const float* rms2_w  = (const float*)d_in[2];
    const float* W_in    = (const float*)d_in[3];
    const float* conv_w  = (const float*)d_in[4];
    const float* conv_b  = (const float*)d_in[5];
    const float* W_xproj = (const float*)d_in[6];
    const float* W_dt    = (const float*)d_in[7];
    const float* b_dt    = (const float*)d_in[8];
    const float* A_log   = (const float*)d_in[9];
    const float* D_skip  = (const float*)d_in[10];
    const float* W_out   = (const float*)d_in[11];
    const float* W_router= (const float*)d_in[12];
    const float* gate_w  = (const float*)d_in[13];
    const float* up_w    = (const float*)d_in[14];
    const float* down_w  = (const float*)d_in[15];
    float* out = (float*)d_out;

    float *p_h1, *p_xz, *p_xc, *p_dbc, *p_delta, *p_y, *p_x2, *p_h2, *p_hg, *p_hu;
    cudaGetSymbolAddress((void**)&p_h1, g_h1);
    cudaGetSymbolAddress((void**)&p_xz, g_xz);
    cudaGetSymbolAddress((void**)&p_xc, g_xc);
    cudaGetSymbolAddress((void**)&p_dbc, g_dbc);
    cudaGetSymbolAddress((void**)&p_delta, g_delta);
    cudaGetSymbolAddress((void**)&p_y, g_y);
    cudaGetSymbolAddress((void**)&p_x2, g_x2);
    cudaGetSymbolAddress((void**)&p_h2, g_h2);
    cudaGetSymbolAddress((void**)&p_hg, g_hg);
    cudaGetSymbolAddress((void**)&p_hu, g_hu);

    reset_kernel<<<1, 32>>>();

    // h1 = rmsnorm(x, rms1_w)
    rmsnorm_kernel<<<LT, 256>>>(x, rms1_w, p_h1, nullptr);

    // xz = h1 @ W_in^T  [2048, 4096]
    sgemm_nt<0><<<dim3((2 * EDIM) / 128, LT / 128), 256>>>(
        p_h1, DMODEL, W_in, DMODEL, 0, p_xz, 2 * EDIM, 2 * EDIM, DMODEL, nullptr);

    // xc = silu(causal depthwise conv(xm) + b)
    conv_silu_kernel<<<(LT * EDIM) / 256, 256>>>(conv_w, conv_b);

    // dbc = xc @ W_xproj^T  [2048, 96]
    sgemm_nt<0><<<dim3(1, LT / 128), 256>>>(
        p_xc, EDIM, W_xproj, EDIM, 0, p_dbc, XPJ, XPJ, EDIM, nullptr);

    // delta = softplus(dt @ W_dt^T + b_dt)  [2048, 2048]
    sgemm_nt<1><<<dim3(EDIM / 128, LT / 128), 256>>>(
        p_dbc, XPJ, W_dt, DTR, 0, p_delta, EDIM, EDIM, DTR, b_dt);

    // selective scan -> y (includes D-skip + silu(z) gating)
    scan_kernel<<<(EDIM * NSTATE) / 256, 256>>>(A_log, D_skip);

    // x2 = x + y @ W_out^T
    sgemm_nt<2><<<dim3(DMODEL / 128, LT / 128), 256>>>(
        p_y, EDIM, W_out, EDIM, 0, p_x2, DMODEL, DMODEL, EDIM, x);

    // h2 = rmsnorm(x2); also seed d_out[:x] with x2 (residual for MoE adds)
    rmsnorm_kernel<<<LT, 256>>>(p_x2, rms2_w, p_h2, out);

    // router: logits -> d_out tail; top-2 selection + counts
    router_kernel<<<LT, 128>>>(W_router, out + (size_t)LT * DMODEL);
    offsets_kernel<<<1, 1>>>();
    scatter_kernel<<<LT / 256, 256>>>();

    // grouped expert GEMMs: gate & up, then silu*up, then down (+weighted scatter)
    sgemm_nt<3><<<dim3(FFD / 128, LT / 128, NEXP), 256>>>(
        p_h2, DMODEL, gate_w, DMODEL, (long)FFD * DMODEL, p_hg, FFD, FFD, DMODEL, nullptr);
    sgemm_nt<3><<<dim3(FFD / 128, LT / 128, NEXP), 256>>>(
        p_h2, DMODEL, up_w, DMODEL, (long)FFD * DMODEL, p_hu, FFD, FFD, DMODEL, nullptr);
    silu_mul_kernel<<<(2 * LT * FFD) / 256, 256>>>();
    sgemm_nt<4><<<dim3(DMODEL / 128, LT / 128, NEXP), 256>>>(
        p_hg, FFD, down_w, FFD, (long)DMODEL * FFD, out, DMODEL, DMODEL, FFD, nullptr);
}

// round 5
// speedup vs baseline: 1.4836x; 1.4836x over previous
#include <cuda_runtime.h>
#include <cuda_fp16.h>
#include <cstdint>
#include <math.h>

#define LT 2048      // tokens (B*L)
#define DMODEL 1024
#define EDIM 2048
#define KCONV 4
#define NSTATE 16
#define DTR 64
#define NEXP 8
#define FFD 2048
#define XPJ 96       // DTR + 2*NSTATE

// ------------------------- static device scratch -------------------------
static __device__ float g_h1[(size_t)LT * DMODEL];
static __device__ float g_xz[(size_t)LT * 2 * EDIM];
static __device__ float g_xc[(size_t)LT * EDIM];
static __device__ float g_dbc[(size_t)LT * XPJ];
static __device__ float g_delta[(size_t)LT * EDIM];
static __device__ float g_y[(size_t)LT * EDIM];
static __device__ float g_x2[(size_t)LT * DMODEL];
static __device__ float g_h2[(size_t)LT * DMODEL];
static __device__ float g_hg[(size_t)2 * LT * FFD];
static __device__ float g_hu[(size_t)2 * LT * FFD];
static __device__ int   g_sel[LT * 2];
static __device__ float g_selw[LT * 2];
static __device__ int   g_counts[NEXP];
static __device__ int   g_offs[NEXP];
static __device__ int   g_cursor[NEXP];
static __device__ int   g_perm[2 * LT];
static __device__ float g_pw[2 * LT];

__device__ __forceinline__ float siluf(float v) { return v / (1.f + expf(-v)); }
__device__ __forceinline__ float softplusf(float v) {
    return v > 0.f ? v + log1pf(expf(-v)) : log1pf(expf(v));
}

__device__ __forceinline__ uint32_t smem_u32(const void* p) {
    uint32_t a;
    asm("{ .reg .u64 t; cvta.to.shared.u64 t, %1; cvt.u32.u64 %0, t; }" : "=r"(a) : "l"(p));
    return a;
}
__device__ __forceinline__ uint32_t packh2(__half a, __half b) {
    __half2 h = __halves2half2(a, b);
    return *reinterpret_cast<uint32_t*>(&h);
}
__device__ __forceinline__ void ldm4(uint32_t* r, uint32_t addr) {
    asm volatile("ldmatrix.sync.aligned.m8n8.x4.shared.b16 {%0,%1,%2,%3}, [%4];"
                 : "=r"(r[0]), "=r"(r[1]), "=r"(r[2]), "=r"(r[3]) : "r"(addr));
}
__device__ __forceinline__ void mma16816(float* d, const uint32_t* a, const uint32_t* b) {
    asm volatile(
        "mma.sync.aligned.m16n8k16.row.col.f32.f16.f16.f32 "
        "{%0,%1,%2,%3}, {%4,%5,%6,%7}, {%8,%9}, {%0,%1,%2,%3};"
        : "+f"(d[0]), "+f"(d[1]), "+f"(d[2]), "+f"(d[3])
        : "r"(a[0]), "r"(a[1]), "r"(a[2]), "r"(a[3]), "r"(b[0]), "r"(b[1]));
}

// ------------------------- small kernels -------------------------
__global__ void reset_kernel() {
    int i = threadIdx.x;
    if (i < NEXP) { g_counts[i] = 0; g_cursor[i] = 0; }
}

__global__ void rmsnorm_kernel(const float* __restrict__ x, const float* __restrict__ w,
                               float* __restrict__ out, float* __restrict__ copy_out) {
    int row = blockIdx.x;
    int tid = threadIdx.x;
    const float* xr = x + (size_t)row * DMODEL;
    float s = 0.f;
    for (int i = tid; i < DMODEL; i += 256) { float v = xr[i]; s += v * v; }
    __shared__ float sh[9];
    for (int o = 16; o > 0; o >>= 1) s += __shfl_xor_sync(0xffffffffu, s, o);
    if ((tid & 31) == 0) sh[tid >> 5] = s;
    __syncthreads();
    if (tid == 0) {
        float t = 0.f;
        for (int i = 0; i < 8; i++) t += sh[i];
        sh[8] = t;
    }
    __syncthreads();
    float scale = rsqrtf(sh[8] * (1.f / DMODEL) + 1e-6f);
    for (int i = tid; i < DMODEL; i += 256) {
        float v = xr[i];
        out[(size_t)row * DMODEL + i] = v * scale * w[i];
        if (copy_out) copy_out[(size_t)row * DMODEL + i] = v;
    }
}

__global__ void conv_silu_kernel(const float* __restrict__ cw, const float* __restrict__ cb) {
    int idx = blockIdx.x * blockDim.x + threadIdx.x;
    if (idx >= LT * EDIM) return;
    int t = idx / EDIM, e = idx - t * EDIM;
    float acc = cb[e];
#pragma unroll
    for (int k = 0; k < KCONV; k++) {
        int tt = t - (KCONV - 1) + k;
        if (tt >= 0) acc = fmaf(cw[e * KCONV + k], g_xz[(size_t)tt * 2 * EDIM + e], acc);
    }
    g_xc[idx] = siluf(acc);
}

__global__ void scan_kernel(const float* __restrict__ A_log, const float* __restrict__ D_skip) {
    int gid = blockIdx.x * blockDim.x + threadIdx.x;
    int e = gid >> 4, n = gid & 15;
    if (e >= EDIM) return;
    float Ae = -expf(A_log[e * NSTATE + n]);
    float Dsk = D_skip[e];
    float h = 0.f;
    for (int t = 0; t < LT; t++) {
        float dlt = g_delta[(size_t)t * EDIM + e];
        float xct = g_xc[(size_t)t * EDIM + e];
        float Bn = g_dbc[(size_t)t * XPJ + DTR + n];
        float Cn = g_dbc[(size_t)t * XPJ + DTR + NSTATE + n];
        float dA = expf(dlt * Ae);
        h = fmaf(dA, h, dlt * Bn * xct);
        float p = h * Cn;
        p += __shfl_xor_sync(0xffffffffu, p, 8);
        p += __shfl_xor_sync(0xffffffffu, p, 4);
        p += __shfl_xor_sync(0xffffffffu, p, 2);
        p += __shfl_xor_sync(0xffffffffu, p, 1);
        if (n == 0) {
            float zt = g_xz[(size_t)t * 2 * EDIM + EDIM + e];
            g_y[(size_t)t * EDIM + e] = (p + Dsk * xct) * siluf(zt);
        }
    }
}

__global__ void router_kernel(const float* __restrict__ Wr, float* __restrict__ out_logits) {
    int t = blockIdx.x;
    int tid = threadIdx.x;
    int g = tid >> 4, l = tid & 15;
    const float* xr = g_h2 + (size_t)t * DMODEL;
    const float* wr = Wr + (size_t)g * DMODEL;
    float acc = 0.f;
    for (int d = l; d < DMODEL; d += 16) acc = fmaf(xr[d], wr[d], acc);
    acc += __shfl_xor_sync(0xffffffffu, acc, 8);
    acc += __shfl_xor_sync(0xffffffffu, acc, 4);
    acc += __shfl_xor_sync(0xffffffffu, acc, 2);
    acc += __shfl_xor_sync(0xffffffffu, acc, 1);
    __shared__ float slog[NEXP];
    if (l == 0) slog[g] = acc;
    __syncthreads();
    if (tid == 0) {
        float lg[NEXP];
        float m = -1e30f;
        for (int e = 0; e < NEXP; e++) {
            lg[e] = slog[e];
            out_logits[(size_t)t * NEXP + e] = lg[e];
            m = fmaxf(m, lg[e]);
        }
        float den = 0.f;
        for (int e = 0; e < NEXP; e++) den += expf(lg[e] - m);
        int i0 = 0; float b0 = -1e30f;
        for (int e = 0; e < NEXP; e++) if (lg[e] > b0) { b0 = lg[e]; i0 = e; }
        int i1 = 0; float b1 = -1e30f;
        for (int e = 0; e < NEXP; e++) if (e != i0 && lg[e] > b1) { b1 = lg[e]; i1 = e; }
        g_sel[t * 2 + 0] = i0;  g_selw[t * 2 + 0] = expf(b0 - m) / den;
        g_sel[t * 2 + 1] = i1;  g_selw[t * 2 + 1] = expf(b1 - m) / den;
        atomicAdd(&g_counts[i0], 1);
        atomicAdd(&g_counts[i1], 1);
    }
}

__global__ void offsets_kernel() {
    if (threadIdx.x == 0) {
        int s = 0;
        for (int e = 0; e < NEXP; e++) { g_offs[e] = s; s += g_counts[e]; }
    }
}

__global__ void scatter_kernel() {
    int t = blockIdx.x * blockDim.x + threadIdx.x;
    if (t >= LT) return;
#pragma unroll
    for (int i = 0; i < 2; i++) {
        int e = g_sel[t * 2 + i];
        int pos = g_offs[e] + atomicAdd(&g_cursor[e], 1);
        g_perm[pos] = t;
        g_pw[pos] = g_selw[t * 2 + i];
    }
}

__global__ void silu_mul_kernel() {
    size_t idx = (size_t)blockIdx.x * blockDim.x + threadIdx.x;
    if (idx >= (size_t)2 * LT * FFD) return;
    float gv = g_hg[idx];
    g_hg[idx] = siluf(gv) * g_hu[idx];
}

// ------------------------- FFMA SGEMM (small GEMMs only) -------------------------
// MODE 0: plain store; MODE 1: C = softplus(acc + aux[col])
template <int MODE>
__global__ void __launch_bounds__(256)
sgemm_nt(const float* __restrict__ A, int lda,
         const float* __restrict__ B, int ldb,
         float* __restrict__ C, int ldc,
         int N, int K,
         const float* __restrict__ aux) {
    const int BM = 128, BN = 128, BK = 8;
    __shared__ float As[BK][BM];
    __shared__ float Bs[BK][BN];

    int tid = threadIdx.x;
    int bx = blockIdx.x, by = blockIdx.y;

    int ar = tid >> 1;
    int ak = (tid & 1) * 4;
    long arow = (long)by * BM + ar;
    int brow = bx * BN + ar;
    bool bvalid = brow < N;
    const float* Aptr = A + arow * (long)lda + ak;
    const float* Bptr = B + (long)brow * ldb + ak;

    float acc[8][8];
#pragma unroll
    for (int i = 0; i < 8; i++)
#pragma unroll
        for (int j = 0; j < 8; j++) acc[i][j] = 0.f;

    int tx = tid & 15, ty = tid >> 4;

    for (int k0 = 0; k0 < K; k0 += BK) {
        float4 av = *(const float4*)(Aptr + k0);
        float4 bv = bvalid ? *(const float4*)(Bptr + k0) : make_float4(0, 0, 0, 0);
        As[ak + 0][ar] = av.x; As[ak + 1][ar] = av.y; As[ak + 2][ar] = av.z; As[ak + 3][ar] = av.w;
        Bs[ak + 0][ar] = bv.x; Bs[ak + 1][ar] = bv.y; Bs[ak + 2][ar] = bv.z; Bs[ak + 3][ar] = bv.w;
        __syncthreads();
        float a[8], b[8];
#pragma unroll
        for (int kk = 0; kk < BK; kk++) {
            *(float4*)&a[0] = *(const float4*)&As[kk][ty * 4];
            *(float4*)&a[4] = *(const float4*)&As[kk][64 + ty * 4];
            *(float4*)&b[0] = *(const float4*)&Bs[kk][tx * 4];
            *(float4*)&b[4] = *(const float4*)&Bs[kk][64 + tx * 4];
#pragma unroll
            for (int i = 0; i < 8; i++)
#pragma unroll
                for (int j = 0; j < 8; j++) acc[i][j] = fmaf(a[i], b[j], acc[i][j]);
        }
        __syncthreads();
    }

#pragma unroll
    for (int i = 0; i < 8; i++) {
        int ml = (i < 4) ? (ty * 4 + i) : (64 + ty * 4 + (i - 4));
#pragma unroll
        for (int jh = 0; jh < 2; jh++) {
            int nl = jh * 64 + tx * 4;
            int col = bx * BN + nl;
            float v0 = acc[i][jh * 4 + 0], v1 = acc[i][jh * 4 + 1];
            float v2 = acc[i][jh * 4 + 2], v3 = acc[i][jh * 4 + 3];
            long row = (long)by * BM + ml;
            if (MODE == 0) {
                if (col < N)
                    *(float4*)(C + row * ldc + col) = make_float4(v0, v1, v2, v3);
            } else {
                *(float4*)(C + row * ldc + col) =
                    make_float4(softplusf(v0 + aux[col + 0]), softplusf(v1 + aux[col + 1]),
                                softplusf(v2 + aux[col + 2]), softplusf(v3 + aux[col + 3]));
            }
        }
    }
}

// ------------------------- fp16x3 mma.sync GEMM -------------------------
// C[M,N] = A[M,K] @ B[N,K]^T in ~fp32 accuracy via Dekker split:
//   A' = [Ah | Al | Ah], B' = [Bh | Bh | Bl] over 48 expanded K per 16 fp32 K.
// Tile 128x128, 16 fp32 K per iter (48 expanded), 8 warps (2M x 4N), 64x32/warp.
// NT layout: both A and B are K-contiguous, so BOTH operands use non-trans
// ldmatrix (B n-rows map directly onto the mma col-major B fragment).
// MODE 0: plain store
// MODE 2: C = acc + aux[row*ldc+col]
// MODE 3: gather A rows via g_perm, store grouped rows
// MODE 4: grouped A rows, epilogue atomicAdd(C[token], w*acc)
#define HG_SB 112            // bytes per smem row (56 halfs: 48 + 8 pad)
#define HG_MAT (128 * HG_SB) // 14336 bytes per matrix tile
#define HG_STAGE (2 * HG_MAT)
#define HG_SMEM (2 * HG_STAGE)  // 57344

template <int MODE>
__global__ void __launch_bounds__(256)
hgemm(const float* __restrict__ A, int lda,
      const float* __restrict__ B, int ldb, long bstride,
      float* __restrict__ C, int ldc,
      int N, int K,
      const float* __restrict__ aux) {
    extern __shared__ char sm[];
    const uint32_t smb = smem_u32(sm);
    const int tid = threadIdx.x;
    const int wid = tid >> 5;
    const int lane = tid & 31;
    const int bx = blockIdx.x, by = blockIdx.y, ez = blockIdx.z;
    const int warpM = wid & 1;       // 2 warps in M
    const int warpN = wid >> 1;      // 4 warps in N

    int cnt = 1 << 30, off = 0;
    const float* Bp = B;
    if (MODE == 3 || MODE == 4) {
        cnt = g_counts[ez];
        off = g_offs[ez];
        if (by * 128 >= cnt) return;
        Bp = B + (long)ez * bstride;
    }

    // ---- staging pointers: 2 chunks/thread of A and B (row, k=4 floats) ----
    const float* apt[2];
    const float* bpt[2];
    bool aval[2];
    int srow[2], skcol[2];
#pragma unroll
    for (int i = 0; i < 2; i++) {
        int idx = i * 256 + tid;
        int row = idx >> 2;          // 0..127
        int k = (idx & 3) * 4;       // 0..12
        srow[i] = row; skcol[i] = k;
        long arow; bool v = true;
        if (MODE == 3) {
            int rr = by * 128 + row;
            v = rr < cnt;
            int tk = v ? g_perm[off + rr] : 0;
            arow = tk;
        } else if (MODE == 4) {
            int rr = by * 128 + row;
            v = rr < cnt;
            arow = v ? (long)off + rr : 0;
        } else arow = (long)by * 128 + row;
        apt[i] = A + arow * (long)lda + k;
        aval[i] = v;
        bpt[i] = Bp + (long)(bx * 128 + row) * ldb + k;
    }

    float4 stA[2], stB[2];
    auto ldg_tile = [&](int kt) {
        int k0 = kt * 16;
#pragma unroll
        for (int i = 0; i < 2; i++) {
            stA[i] = aval[i] ? *(const float4*)(apt[i] + k0) : make_float4(0, 0, 0, 0);
            stB[i] = *(const float4*)(bpt[i] + k0);
        }
    };
    auto sts_stage = [&](int s) {
        char* base = sm + s * HG_STAGE;
#pragma unroll
        for (int i = 0; i < 2; i++) {
            int ro = srow[i] * HG_SB + skcol[i] * 2;
            {
                float4 v = stA[i];
                __half h0 = __float2half_rn(v.x), h1 = __float2half_rn(v.y);
                __half h2 = __float2half_rn(v.z), h3 = __float2half_rn(v.w);
                uint32_t hiA = packh2(h0, h1), hiB = packh2(h2, h3);
                __half l0 = __float2half_rn(v.x - __half2float(h0));
                __half l1 = __float2half_rn(v.y - __half2float(h1));
                __half l2 = __float2half_rn(v.z - __half2float(h2));
                __half l3 = __float2half_rn(v.w - __half2float(h3));
                uint32_t loA = packh2(l0, l1), loB = packh2(l2, l3);
                *(uint2*)(base + ro)      = make_uint2(hiA, hiB);   // Ah @ [0,16)
                *(uint2*)(base + ro + 32) = make_uint2(loA, loB);   // Al @ [16,32)
                *(uint2*)(base + ro + 64) = make_uint2(hiA, hiB);   // Ah @ [32,48)
            }
            {
                float4 v = stB[i];
                __half h0 = __float2half_rn(v.x), h1 = __float2half_rn(v.y);
                __half h2 = __float2half_rn(v.z), h3 = __float2half_rn(v.w);
                uint32_t hiA = packh2(h0, h1), hiB = packh2(h2, h3);
                __half l0 = __float2half_rn(v.x - __half2float(h0));
                __half l1 = __float2half_rn(v.y - __half2float(h1));
                __half l2 = __float2half_rn(v.z - __half2float(h2));
                __half l3 = __float2half_rn(v.w - __half2float(h3));
                uint32_t loA = packh2(l0, l1), loB = packh2(l2, l3);
                char* bb = base + HG_MAT;
                *(uint2*)(bb + ro)      = make_uint2(hiA, hiB);     // Bh @ [0,16)
                *(uint2*)(bb + ro + 32) = make_uint2(hiA, hiB);     // Bh @ [16,32)
                *(uint2*)(bb + ro + 64) = make_uint2(loA, loB);     // Bl @ [32,48)
            }
        }
    };

    // ldmatrix base addresses (byte offsets within a stage)
    const uint32_t aBase = smb + (warpM * 64 + (lane & 15)) * HG_SB + (lane >> 4) * 16;
    const uint32_t bBase = smb + HG_MAT +
        (warpN * 32 + ((lane >> 4) << 3) + (lane & 7)) * HG_SB + ((lane >> 3) & 1) * 16;

    float acc[4][4][4];
#pragma unroll
    for (int mt = 0; mt < 4; mt++)
#pragma unroll
        for (int nt = 0; nt < 4; nt++)
#pragma unroll
            for (int q = 0; q < 4; q++) acc[mt][nt][q] = 0.f;

    const int ntiles = K >> 4;

    ldg_tile(0);
    sts_stage(0);
    __syncthreads();

    for (int kt = 0; kt < ntiles; kt++) {
        int cur = kt & 1;
        if (kt + 1 < ntiles) ldg_tile(kt + 1);
        uint32_t st = cur * HG_STAGE;
#pragma unroll
        for (int ks = 0; ks < 3; ks++) {
            uint32_t af[4][4];
#pragma unroll
            for (int mt = 0; mt < 4; mt++)
                ldm4(af[mt], aBase + st + mt * (16 * HG_SB) + ks * 32);
            uint32_t b0[4], b1[4];
            ldm4(b0, bBase + st + ks * 32);
            ldm4(b1, bBase + st + 16 * HG_SB + ks * 32);
#pragma unroll
            for (int mt = 0; mt < 4; mt++) {
                mma16816(acc[mt][0], af[mt], &b0[0]);
                mma16816(acc[mt][1], af[mt], &b0[2]);
                mma16816(acc[mt][2], af[mt], &b1[0]);
                mma16816(acc[mt][3], af[mt], &b1[2]);
            }
        }
        if (kt + 1 < ntiles) {
            sts_stage(1 - cur);
            __syncthreads();
        }
    }

    // ------------- epilogue: direct frag stores -------------
#pragma unroll
    for (int mt = 0; mt < 4; mt++) {
#pragma unroll
        for (int h = 0; h < 2; h++) {
            int rloc = warpM * 64 + mt * 16 + (lane >> 2) + h * 8;
            int rr = by * 128 + rloc;
#pragma unroll
            for (int nt = 0; nt < 4; nt++) {
                int gc = bx * 128 + warpN * 32 + nt * 8 + (lane & 3) * 2;
                float v0 = acc[mt][nt][h * 2 + 0];
                float v1 = acc[mt][nt][h * 2 + 1];
                if (MODE == 0) {
                    *(float2*)(C + (long)rr * ldc + gc) = make_float2(v0, v1);
                } else if (MODE == 2) {
                    float2 a2 = *(const float2*)(aux + (long)rr * ldc + gc);
                    *(float2*)(C + (long)rr * ldc + gc) = make_float2(v0 + a2.x, v1 + a2.y);
                } else if (MODE == 3) {
                    if (rr < cnt)
                        *(float2*)(C + ((long)off + rr) * ldc + gc) = make_float2(v0, v1);
                } else {  // MODE 4
                    if (rr < cnt) {
                        int tok = g_perm[off + rr];
                        float w = g_pw[off + rr];
                        float* o = C + (long)tok * ldc + gc;
                        atomicAdd(o + 0, w * v0);
                        atomicAdd(o + 1, w * v1);
                    }
                }
            }
        }
    }
}

// ------------------------- host launcher -------------------------
extern "C" void kernel_launch(void* const* d_in, const int* in_sizes, int n_in,
                              void* d_out, int out_size) {
    const float* x       = (const float*)d_in[0];
    const float* rms1_w  = (const float*)d_in[1];
    const float* rms2_w  = (const float*)d_in[2];
    const float* W_in    = (const float*)d_in[3];
    const float* conv_w  = (const float*)d_in[4];
    const float* conv_b  = (const float*)d_in[5];
    const float* W_xproj = (const float*)d_in[6];
    const float* W_dt    = (const float*)d_in[7];
    const float* b_dt    = (const float*)d_in[8];
    const float* A_log   = (const float*)d_in[9];
    const float* D_skip  = (const float*)d_in[10];
    const float* W_out   = (const float*)d_in[11];
    const float* W_router= (const float*)d_in[12];
    const float* gate_w  = (const float*)d_in[13];
    const float* up_w    = (const float*)d_in[14];
    const float* down_w  = (const float*)d_in[15];
    float* out = (float*)d_out;

    float *p_h1, *p_xz, *p_xc, *p_dbc, *p_delta, *p_y, *p_x2, *p_h2, *p_hg, *p_hu;
    cudaGetSymbolAddress((void**)&p_h1, g_h1);
    cudaGetSymbolAddress((void**)&p_xz, g_xz);
    cudaGetSymbolAddress((void**)&p_xc, g_xc);
    cudaGetSymbolAddress((void**)&p_dbc, g_dbc);
    cudaGetSymbolAddress((void**)&p_delta, g_delta);
    cudaGetSymbolAddress((void**)&p_y, g_y);
    cudaGetSymbolAddress((void**)&p_x2, g_x2);
    cudaGetSymbolAddress((void**)&p_h2, g_h2);
    cudaGetSymbolAddress((void**)&p_hg, g_hg);
    cudaGetSymbolAddress((void**)&p_hu, g_hu);

    cudaFuncSetAttribute(hgemm<0>, cudaFuncAttributeMaxDynamicSharedMemorySize, HG_SMEM);
    cudaFuncSetAttribute(hgemm<2>, cudaFuncAttributeMaxDynamicSharedMemorySize, HG_SMEM);
    cudaFuncSetAttribute(hgemm<3>, cudaFuncAttributeMaxDynamicSharedMemorySize, HG_SMEM);
    cudaFuncSetAttribute(hgemm<4>, cudaFuncAttributeMaxDynamicSharedMemorySize, HG_SMEM);

    reset_kernel<<<1, 32>>>();

    // h1 = rmsnorm(x, rms1_w)
    rmsnorm_kernel<<<LT, 256>>>(x, rms1_w, p_h1, nullptr);

    // xz = h1 @ W_in^T  [2048, 4096]  (tensor)
    hgemm<0><<<dim3((2 * EDIM) / 128, LT / 128), 256, HG_SMEM>>>(
        p_h1, DMODEL, W_in, DMODEL, 0, p_xz, 2 * EDIM, 2 * EDIM, DMODEL, nullptr);

    // xc = silu(causal depthwise conv(xm) + b)
    conv_silu_kernel<<<(LT * EDIM) / 256, 256>>>(conv_w, conv_b);

    // dbc = xc @ W_xproj^T  [2048, 96]  (FFMA, tiny)
    sgemm_nt<0><<<dim3(1, LT / 128), 256>>>(
        p_xc, EDIM, W_xproj, EDIM, p_dbc, XPJ, XPJ, EDIM, nullptr);

    // delta = softplus(dt @ W_dt^T + b_dt)  [2048, 2048]  (FFMA, K=64)
    sgemm_nt<1><<<dim3(EDIM / 128, LT / 128), 256>>>(
        p_dbc, XPJ, W_dt, DTR, p_delta, EDIM, EDIM, DTR, b_dt);

    // selective scan -> y
    scan_kernel<<<(EDIM * NSTATE) / 256, 256>>>(A_log, D_skip);

    // x2 = x + y @ W_out^T  (tensor, residual epilogue)
    hgemm<2><<<dim3(DMODEL / 128, LT / 128), 256, HG_SMEM>>>(
        p_y, EDIM, W_out, EDIM, 0, p_x2, DMODEL, DMODEL, EDIM, x);

    // h2 = rmsnorm(x2); copy x2 residual into d_out
    rmsnorm_kernel<<<LT, 256>>>(p_x2, rms2_w, p_h2, out);

    // router + grouping
    router_kernel<<<LT, 128>>>(W_router, out + (size_t)LT * DMODEL);
    offsets_kernel<<<1, 1>>>();
    scatter_kernel<<<LT / 256, 256>>>();

    // grouped expert GEMMs (tensor)
    hgemm<3><<<dim3(FFD / 128, (2 * LT) / 128, NEXP), 256, HG_SMEM>>>(
        p_h2, DMODEL, gate_w, DMODEL, (long)FFD * DMODEL, p_hg, FFD, FFD, DMODEL, nullptr);
    hgemm<3><<<dim3(FFD / 128, (2 * LT) / 128, NEXP), 256, HG_SMEM>>>(
        p_h2, DMODEL, up_w, DMODEL, (long)FFD * DMODEL, p_hu, FFD, FFD, DMODEL, nullptr);
    silu_mul_kernel<<<(2 * LT * FFD) / 256, 256>>>();
    hgemm<4><<<dim3(DMODEL / 128, (2 * LT) / 128, NEXP), 256, HG_SMEM>>>(
        p_hg, FFD, down_w, FFD, (long)DMODEL * FFD, out, DMODEL, DMODEL, FFD, nullptr);
}